// round 5
// baseline (speedup 1.0000x reference)
#include <cuda_runtime.h>

// IF spiking neuron forward (R5):
//   x: [T=8, N=4194304] fp32, thresh: [1] fp32
//   mem = 0.5*thr; per t: m = mem + x[t]; s = (m>=thr); out[t] = s*thr; mem = m - s*thr
//
// R5 = R2 shape (1 float4/thread, TPB=256) + forced 32-reg budget via
// __launch_bounds__(256, 8) to pin occupancy at ~81% (8 CTAs/SM) WITH the
// __ldcs/__stcs streaming hints (which at default budget inflated regs to 40
// and cost occupancy in R4). DRAM% tracked occupancy monotonically R2-R4.

#define T_STEPS 8
#define N_NEURONS (256 / T_STEPS * 512 * 16 * 16)   // 4,194,304
#define N4 (N_NEURONS / 4)                           // 1,048,576 float4 per timestep
#define TPB 256

__global__ __launch_bounds__(TPB, 8) void if_forward_kernel(
    const float4* __restrict__ x,
    const float* __restrict__ thresh,
    float4* __restrict__ out)
{
    const int i = blockIdx.x * TPB + threadIdx.x;  // grid exactly covers N4
    const float thr = __ldg(thresh);

    // Front-batch the 8 timestep loads (ptxas schedules within 32-reg budget).
    float4 xv[T_STEPS];
#pragma unroll
    for (int t = 0; t < T_STEPS; t++) {
        xv[t] = __ldcs(&x[(size_t)t * N4 + i]);
    }

    float m0 = 0.5f * thr, m1 = m0, m2 = m0, m3 = m0;

#pragma unroll
    for (int t = 0; t < T_STEPS; t++) {
        m0 += xv[t].x;
        m1 += xv[t].y;
        m2 += xv[t].z;
        m3 += xv[t].w;
        float4 sp;
        sp.x = (m0 >= thr) ? thr : 0.0f;
        sp.y = (m1 >= thr) ? thr : 0.0f;
        sp.z = (m2 >= thr) ? thr : 0.0f;
        sp.w = (m3 >= thr) ? thr : 0.0f;
        m0 -= sp.x;
        m1 -= sp.y;
        m2 -= sp.z;
        m3 -= sp.w;
        __stcs(&out[(size_t)t * N4 + i], sp);
    }
}

extern "C" void kernel_launch(void* const* d_in, const int* in_sizes, int n_in,
                              void* d_out, int out_size) {
    const float4* x = (const float4*)d_in[0];
    const float* thresh = (const float*)d_in[1];
    float4* out = (float4*)d_out;

    const int blocks = N4 / TPB;  // 4096, exact
    if_forward_kernel<<<blocks, TPB>>>(x, thresh, out);
}

// round 6
// speedup vs baseline: 1.0603x; 1.0603x over previous
#include <cuda_runtime.h>

// IF spiking neuron forward (R6 = R2 verbatim — measured-best config):
//   x: [T=8, N=4194304] fp32, thresh: [1] fp32
//   mem = 0.5*thr; per t: m = mem + x[t]; s = (m>=thr); out[t] = s*thr; mem = m - s*thr
//
// Pure 1:1 streaming kernel (128 MiB read + 128 MiB write, single touch).
// A/B evidence across R2-R5:
//   - R2 (this shape): 36.7us, DRAM 73.6%, occ 81%            <- best
//   - R3 (ITEMS=2, 77 regs, occ 31%): 38.3us, DRAM 70.6%      <- per-thread MLP
//     doesn't pay for occupancy loss
//   - R4 (TPB512 + ldcs/stcs, 40 regs): 37.1us, DRAM 72.9%
//   - R5 (R2 + ldcs/stcs): 43.1us, DRAM 69.8%                 <- streaming hints
//     actively hurt this mixed R/W stream at same occ/regs
// 5.8 TB/s ~= mixed-stream HBM turnaround ceiling; no traffic reduction exists.

#define T_STEPS 8
#define N_NEURONS (256 / T_STEPS * 512 * 16 * 16)   // 4,194,304
#define N4 (N_NEURONS / 4)                           // 1,048,576 float4 per timestep
#define TPB 256

__global__ __launch_bounds__(TPB) void if_forward_kernel(
    const float4* __restrict__ x,
    const float* __restrict__ thresh,
    float4* __restrict__ out)
{
    const int i = blockIdx.x * TPB + threadIdx.x;  // grid exactly covers N4
    const float thr = __ldg(thresh);

    // Front-batch the 8 timestep loads (ptxas fits this in 32 regs with
    // its own interleaving; measured MLP is sufficient at 81% occupancy).
    float4 xv[T_STEPS];
#pragma unroll
    for (int t = 0; t < T_STEPS; t++) {
        xv[t] = x[(size_t)t * N4 + i];
    }

    float m0 = 0.5f * thr, m1 = m0, m2 = m0, m3 = m0;

#pragma unroll
    for (int t = 0; t < T_STEPS; t++) {
        m0 += xv[t].x;
        m1 += xv[t].y;
        m2 += xv[t].z;
        m3 += xv[t].w;
        float4 sp;
        sp.x = (m0 >= thr) ? thr : 0.0f;
        sp.y = (m1 >= thr) ? thr : 0.0f;
        sp.z = (m2 >= thr) ? thr : 0.0f;
        sp.w = (m3 >= thr) ? thr : 0.0f;
        m0 -= sp.x;
        m1 -= sp.y;
        m2 -= sp.z;
        m3 -= sp.w;
        out[(size_t)t * N4 + i] = sp;
    }
}

extern "C" void kernel_launch(void* const* d_in, const int* in_sizes, int n_in,
                              void* d_out, int out_size) {
    const float4* x = (const float4*)d_in[0];
    const float* thresh = (const float*)d_in[1];
    float4* out = (float4*)d_out;

    const int blocks = N4 / TPB;  // 16384, exact
    if_forward_kernel<<<blocks, TPB>>>(x, thresh, out);
}